// round 1
// baseline (speedup 1.0000x reference)
#include <cuda_runtime.h>

// x: (128, 32, 2, 64, 64) fp32 contiguous.
// For tile bh in [0, 4096): theta0 = x + bh*8192, theta1 = theta0 + 4096.
// plaq[i][j] = t0[i][j] + t1[(i+1)%64][j] - t0[i][(j+1)%64] - t1[i][j]
// out[bh] = mean(cos(plaq))

#define THREADS 256

__global__ __launch_bounds__(THREADS) void plaq_trace_kernel(
    const float* __restrict__ x, float* __restrict__ out)
{
    const int bh = blockIdx.x;
    const float* __restrict__ t0 = x + (size_t)bh * 8192;
    const float* __restrict__ t1 = t0 + 4096;

    __shared__ float s0[4096];
    __shared__ float s1[4096];
    __shared__ float warp_sums[THREADS / 32];

    const int tid = threadIdx.x;

    // Stage both 64x64 tiles into smem with float4 loads (coalesced, each
    // DRAM byte touched exactly once).
    {
        const float4* __restrict__ v0 = (const float4*)t0;
        const float4* __restrict__ v1 = (const float4*)t1;
        float4* __restrict__ d0 = (float4*)s0;
        float4* __restrict__ d1 = (float4*)s1;
        #pragma unroll
        for (int v = tid; v < 1024; v += THREADS) {
            d0[v] = v0[v];
            d1[v] = v1[v];
        }
    }
    __syncthreads();

    float sum = 0.0f;
    #pragma unroll
    for (int e = tid; e < 4096; e += THREADS) {
        const int i  = e >> 6;
        const int j  = e & 63;
        const int jp = (j + 1) & 63;
        const int ip = (i + 1) & 63;
        // stride-1 smem accesses across a warp -> conflict-free
        const float plaq = s0[e] + s1[(ip << 6) | j] - s0[(i << 6) | jp] - s1[e];
        sum += __cosf(plaq);
    }

    // Warp reduction
    #pragma unroll
    for (int off = 16; off > 0; off >>= 1)
        sum += __shfl_xor_sync(0xFFFFFFFFu, sum, off);

    const int wid = tid >> 5;
    const int lid = tid & 31;
    if (lid == 0) warp_sums[wid] = sum;
    __syncthreads();

    if (wid == 0) {
        float s = (lid < (THREADS / 32)) ? warp_sums[lid] : 0.0f;
        #pragma unroll
        for (int off = 4; off > 0; off >>= 1)
            s += __shfl_xor_sync(0xFFFFFFFFu, s, off);
        if (lid == 0) out[bh] = s * (1.0f / 4096.0f);
    }
}

extern "C" void kernel_launch(void* const* d_in, const int* in_sizes, int n_in,
                              void* d_out, int out_size)
{
    const float* x = (const float*)d_in[0];
    float* out = (float*)d_out;
    // 128 * 32 = 4096 (b,h) tiles, one CTA each
    plaq_trace_kernel<<<4096, THREADS>>>(x, out);
}

// round 2
// speedup vs baseline: 1.0755x; 1.0755x over previous
#include <cuda_runtime.h>
#include <cstdint>

// x: (128, 32, 2, 64, 64) fp32 contiguous -> 4096 tiles of (2, 64, 64).
// plaq[i][j] = t0[i][j] + t1[(i+1)%64][j] - t0[i][(j+1)%64] - t1[i][j]
// out[tile] = mean(cos(plaq))
//
// Strategy: quasi-persistent CTAs with cp.async double-buffered tile pipeline
// so DRAM loads for tile k+1 overlap compute of tile k. 64 KB dynamic smem
// (2 x 32 KB tile buffers) -> 3 CTAs/SM, ~96 KB outstanding DRAM bytes per SM.

#define THREADS 256
#define NUM_TILES 4096
#define TILE_FLOATS 8192              // 2 * 64 * 64
#define GRID_CTAS 456                 // 152 SMs * 3 CTAs/SM

__device__ __forceinline__ void cp_async16(float* dst_smem, const float* src) {
    uint32_t d = (uint32_t)__cvta_generic_to_shared(dst_smem);
    asm volatile("cp.async.cg.shared.global [%0], [%1], 16;\n"
                 :: "r"(d), "l"(src));
}

__device__ __forceinline__ void cp_commit() {
    asm volatile("cp.async.commit_group;\n" ::: "memory");
}

template <int N>
__device__ __forceinline__ void cp_wait() {
    asm volatile("cp.async.wait_group %0;\n" :: "n"(N) : "memory");
}

// Prefetch one full tile (8192 floats = 2048 float4) into smem buffer.
__device__ __forceinline__ void prefetch_tile(float* smbuf, const float* gtile, int tid) {
    #pragma unroll
    for (int j = 0; j < 8; j++) {
        int v = tid + j * THREADS;          // float4 index, 0..2047
        cp_async16(smbuf + v * 4, gtile + v * 4);
    }
}

__global__ __launch_bounds__(THREADS) void plaq_trace_pipe_kernel(
    const float* __restrict__ x, float* __restrict__ out)
{
    extern __shared__ float sm[];           // 2 * TILE_FLOATS floats
    __shared__ float warp_sums[THREADS / 32];

    const int tid  = threadIdx.x;
    const int wid  = tid >> 5;
    const int lane = tid & 31;

    int t = blockIdx.x;
    if (t >= NUM_TILES) return;

    // Prime the pipeline: prefetch first tile into buffer 0.
    prefetch_tile(sm, x + (size_t)t * TILE_FLOATS, tid);
    cp_commit();

    int buf = 0;
    while (true) {
        const int tn = t + GRID_CTAS;
        const bool has_next = (tn < NUM_TILES);

        if (has_next) {
            // Kick off next tile into the other buffer, then wait for current.
            prefetch_tile(sm + (buf ^ 1) * TILE_FLOATS,
                          x + (size_t)tn * TILE_FLOATS, tid);
            cp_commit();
            cp_wait<1>();                   // current tile's group complete
        } else {
            cp_wait<0>();
        }
        __syncthreads();

        const float* __restrict__ s0 = sm + buf * TILE_FLOATS;
        const float* __restrict__ s1 = s0 + 4096;

        float sum = 0.0f;
        #pragma unroll
        for (int e = tid; e < 4096; e += THREADS) {
            const int i  = e >> 6;
            const int j  = e & 63;
            const int jp = (j + 1) & 63;
            const int ip = (i + 1) & 63;
            const float plaq = s0[e] + s1[(ip << 6) | j] - s0[(i << 6) | jp] - s1[e];
            sum += __cosf(plaq);
        }

        // Warp reduce
        #pragma unroll
        for (int off = 16; off > 0; off >>= 1)
            sum += __shfl_xor_sync(0xFFFFFFFFu, sum, off);
        if (lane == 0) warp_sums[wid] = sum;
        __syncthreads();                    // also protects buffer reuse

        if (wid == 0) {
            float s = (lane < (THREADS / 32)) ? warp_sums[lane] : 0.0f;
            #pragma unroll
            for (int off = 4; off > 0; off >>= 1)
                s += __shfl_xor_sync(0xFFFFFFFFu, s, off);
            if (lane == 0) out[t] = s * (1.0f / 4096.0f);
        }

        if (!has_next) break;
        buf ^= 1;
        t = tn;
        // Note: buffer we are about to prefetch into on the next iteration is
        // the one we just computed from; the __syncthreads above ensures all
        // threads finished reading it.
    }
}

extern "C" void kernel_launch(void* const* d_in, const int* in_sizes, int n_in,
                              void* d_out, int out_size)
{
    const float* x = (const float*)d_in[0];
    float* out = (float*)d_out;

    static bool attr_set = false;
    if (!attr_set) {
        cudaFuncSetAttribute(plaq_trace_pipe_kernel,
                             cudaFuncAttributeMaxDynamicSharedMemorySize,
                             2 * TILE_FLOATS * sizeof(float));
        attr_set = true;
    }

    plaq_trace_pipe_kernel<<<GRID_CTAS, THREADS,
                             2 * TILE_FLOATS * sizeof(float)>>>(x, out);
}

// round 3
// speedup vs baseline: 1.1648x; 1.0830x over previous
#include <cuda_runtime.h>

// x: (128, 32, 2, 64, 64) fp32 -> 4096 tiles of (2, 64, 64).
// plaq[i][j] = t0[i][j] + t1[(i+1)%64][j] - t0[i][(j+1)%64] - t1[i][j]
// out[tile] = mean(cos(plaq))
//
// No smem staging: pure-LDG kernel. Each thread handles 4 float4 "groups"
// (16 elements) of one tile with 12 independent LDG.128 up front (MLP=12).
// j+1 roll resolved in-register (3/4 inside the float4, 1/4 via lane shuffle:
// a warp covers 2 rows of 16 lanes; neighbor lane = (l&16)|((l+1)&15), which
// also handles the j=63 -> j=0 torus wrap). t1's second read (row i+1) hits
// L1 (48 KB tile working set << L1D).

#define THREADS 256

__global__ __launch_bounds__(THREADS) void plaq_trace_reg_kernel(
    const float4* __restrict__ x4, float* __restrict__ out)
{
    const int t = blockIdx.x;
    const float4* __restrict__ t0 = x4 + (size_t)t * 2048;  // 1024 float4 each
    const float4* __restrict__ t1 = t0 + 1024;

    const int tid  = threadIdx.x;
    const int lane = tid & 31;
    const int wid  = tid >> 5;

    float4 A0[4], A1[4], B1[4];

    // 12 independent 16B loads, all issued before any consumption.
    #pragma unroll
    for (int k = 0; k < 4; k++) {
        const int g  = tid + k * THREADS;        // float4 group 0..1023
        const int i  = g >> 4;                   // row 0..63
        const int jg = g & 15;                   // float4 col 0..15
        const int g1 = (((i + 1) & 63) << 4) | jg;
        A0[k] = t0[g];
        A1[k] = t1[g];
        B1[k] = t1[g1];
    }

    // Lane to the right within this row's 16-lane segment (with torus wrap).
    const int src = (lane & 16) | ((lane + 1) & 15);

    float sum = 0.0f;
    #pragma unroll
    for (int k = 0; k < 4; k++) {
        const float nx = __shfl_sync(0xFFFFFFFFu, A0[k].x, src);
        sum += __cosf(A0[k].x + B1[k].x - A0[k].y - A1[k].x);
        sum += __cosf(A0[k].y + B1[k].y - A0[k].z - A1[k].y);
        sum += __cosf(A0[k].z + B1[k].z - A0[k].w - A1[k].z);
        sum += __cosf(A0[k].w + B1[k].w - nx      - A1[k].w);
    }

    // Warp reduce
    #pragma unroll
    for (int off = 16; off > 0; off >>= 1)
        sum += __shfl_xor_sync(0xFFFFFFFFu, sum, off);

    __shared__ float warp_sums[THREADS / 32];
    if (lane == 0) warp_sums[wid] = sum;
    __syncthreads();

    if (wid == 0) {
        float s = (lane < (THREADS / 32)) ? warp_sums[lane] : 0.0f;
        #pragma unroll
        for (int off = 4; off > 0; off >>= 1)
            s += __shfl_xor_sync(0xFFFFFFFFu, s, off);
        if (lane == 0) out[t] = s * (1.0f / 4096.0f);
    }
}

extern "C" void kernel_launch(void* const* d_in, const int* in_sizes, int n_in,
                              void* d_out, int out_size)
{
    const float4* x4 = (const float4*)d_in[0];
    float* out = (float*)d_out;
    plaq_trace_reg_kernel<<<4096, THREADS>>>(x4, out);
}